// round 15
// baseline (speedup 1.0000x reference)
#include <cuda_runtime.h>
#include <cstdint>

#define EPSV 1e-5f

__device__ __align__(16) float g_Sp[16*32*4096];   // per-slice partial Grams
__device__ __align__(16) float g_csp[16*32*64];    // per-slice partial col sums
__device__ __align__(16) float g_wm[32*4096];
__device__ __align__(16) float g_mean[2048];
__device__ __align__(16) float g_svw[4096];
__device__ __align__(16) float g_svm[64];
__device__ __align__(16) float g_A[32*4096];       // stored tf32-rounded
__device__ __align__(16) float g_bp[2048];

__device__ __forceinline__ unsigned t32(float x) {
    unsigned r; asm("cvt.rna.tf32.f32 %0,%1;" : "=r"(r) : "f"(x)); return r;
}
__device__ __forceinline__ void mma8(float* c, const unsigned* a, unsigned b0, unsigned b1) {
    asm("mma.sync.aligned.m16n8k8.row.col.f32.tf32.tf32.f32 "
        "{%0,%1,%2,%3},{%4,%5,%6,%7},{%8,%9},{%0,%1,%2,%3};"
        : "+f"(c[0]), "+f"(c[1]), "+f"(c[2]), "+f"(c[3])
        : "r"(a[0]), "r"(a[1]), "r"(a[2]), "r"(a[3]), "r"(b0), "r"(b1));
}
__device__ __forceinline__ void cpa16(unsigned d, const float* s) {
    asm volatile("cp.async.ca.shared.global [%0],[%1],16;" :: "r"(d), "l"(s));
}

// ---------------- K1: Gram partials, mma.tf32, 3-stage cp.async --------------
// grid (16 slices, 32 batches), 256 thr; block = 64 rows x 1024 cols, chunk 64.
__global__ __launch_bounds__(256) void k1_gram(const float* __restrict__ x,
                                               const int* __restrict__ idx) {
    extern __shared__ float sm[];            // 3 stages of 64*68
    __shared__ const float* rowp[64];
    int sl = blockIdx.x, b = blockIdx.y, t = threadIdx.x;
    if (t < 64)
        rowp[t] = x + ((size_t)(b * 256 + idx[4 * t + (sl >> 2)])) * 4096 + (sl & 3) * 1024;
    __syncthreads();
    int r = t >> 2, fq = t & 3;
    const float* rp = rowp[r];
    unsigned sb = (unsigned)__cvta_generic_to_shared(sm);
#pragma unroll
    for (int s = 0; s < 2; s++) {
        unsigned d = sb + (s * 4352 + r * 68 + fq * 4) * 4;
        const float* src = rp + s * 64 + fq * 4;
#pragma unroll
        for (int j = 0; j < 4; j++) cpa16(d + j * 64, src + j * 16);
        asm volatile("cp.async.commit_group;");
    }
    int lane = t & 31, w = t >> 5, g = lane >> 2, tg = lane & 3;
    int mbase = (w & 3) * 16, nbase = (w >> 2) * 32;
    float acc[4][4];
#pragma unroll
    for (int j = 0; j < 4; j++)
#pragma unroll
        for (int i = 0; i < 4; i++) acc[j][i] = 0.f;
    float cs = 0.f;
    for (int c = 0; c < 16; c++) {
        if (c < 15) { asm volatile("cp.async.wait_group 1;"); }
        else        { asm volatile("cp.async.wait_group 0;"); }
        __syncthreads();
        const float* Xc = sm + (c % 3) * 4352;
#pragma unroll
        for (int j = 0; j < 4; j++) {
            float4 v = *(const float4*)(Xc + r * 68 + fq * 16 + j * 4);
            cs += v.x + v.y + v.z + v.w;
        }
#pragma unroll
        for (int k0 = 0; k0 < 8; k0++) {
            unsigned a[4];
            a[0] = __float_as_uint(Xc[(mbase + g) * 68 + k0 * 8 + tg]);
            a[1] = __float_as_uint(Xc[(mbase + g + 8) * 68 + k0 * 8 + tg]);
            a[2] = __float_as_uint(Xc[(mbase + g) * 68 + k0 * 8 + tg + 4]);
            a[3] = __float_as_uint(Xc[(mbase + g + 8) * 68 + k0 * 8 + tg + 4]);
#pragma unroll
            for (int j = 0; j < 4; j++) {
                unsigned b0 = __float_as_uint(Xc[(nbase + j * 8 + g) * 68 + k0 * 8 + tg]);
                unsigned b1 = __float_as_uint(Xc[(nbase + j * 8 + g) * 68 + k0 * 8 + tg + 4]);
                mma8(acc[j], a, b0, b1);
            }
        }
        if (c < 14) {
            unsigned d = sb + (((c + 2) % 3) * 4352 + r * 68 + fq * 4) * 4;
            const float* src = rp + (c + 2) * 64 + fq * 4;
#pragma unroll
            for (int j = 0; j < 4; j++) cpa16(d + j * 64, src + j * 16);
            asm volatile("cp.async.commit_group;");
        }
    }
    float* dst = g_Sp + (size_t)(sl * 32 + b) * 4096;
#pragma unroll
    for (int j = 0; j < 4; j++) {
        int col = nbase + j * 8 + 2 * tg;
        *(float2*)(dst + (mbase + g) * 64 + col)     = make_float2(acc[j][0], acc[j][1]);
        *(float2*)(dst + (mbase + g + 8) * 64 + col) = make_float2(acc[j][2], acc[j][3]);
    }
    cs += __shfl_down_sync(0xffffffffu, cs, 2, 4);
    cs += __shfl_down_sync(0xffffffffu, cs, 1, 4);
    if (fq == 0) g_csp[(sl * 32 + b) * 64 + r] = cs;
}

// ---- 64x64 smem matmul, LD=68, A float4, 512 threads (2x4 thread tile) ------
#define MMH(COMP, BK) { \
    float b0 = (BK)[0], b1 = (BK)[16], b2 = (BK)[32], b3 = (BK)[48]; \
    acc[0] += va0.COMP*b0; acc[1] += va0.COMP*b1; acc[2] += va0.COMP*b2; acc[3] += va0.COMP*b3; \
    acc[4] += va1.COMP*b0; acc[5] += va1.COMP*b1; acc[6] += va1.COMP*b2; acc[7] += va1.COMP*b3; }

__device__ __forceinline__ void mm64h(const float* __restrict__ A,
                                      const float* __restrict__ B,
                                      float* __restrict__ C, int t, bool fin) {
    int r0 = (t >> 4) << 1, c0 = t & 15;
    float acc[8];
#pragma unroll
    for (int i = 0; i < 8; i++) acc[i] = 0.f;
#pragma unroll
    for (int k4 = 0; k4 < 16; k4++) {
        float4 va0 = *(const float4*)(A + (r0 + 0) * 68 + k4 * 4);
        float4 va1 = *(const float4*)(A + (r0 + 1) * 68 + k4 * 4);
        const float* Bk = B + k4 * 4 * 68 + c0;
        MMH(x, Bk); Bk += 68;
        MMH(y, Bk); Bk += 68;
        MMH(z, Bk); Bk += 68;
        MMH(w, Bk);
    }
#pragma unroll
    for (int i = 0; i < 2; i++)
#pragma unroll
        for (int j = 0; j < 4; j++) {
            int ci = (r0 + i) * 68 + c0 + 16 * j;
            C[ci] = fin ? (1.5f * A[ci] - 0.5f * acc[i * 4 + j]) : acc[i * 4 + j];
        }
}

// -------- K2a: reduce partials -> sigma -> Newton-Schulz -> wm (512 thr) -----
__global__ __launch_bounds__(512) void k2a_ns() {
    extern __shared__ float sm[];
    float* sigN = sm;
    float* bA = sm + 4352;
    float* bB = sm + 8704;
    float* bC = sm + 13056;
    __shared__ float smean[64];
    __shared__ float s_tr;
    int b = blockIdx.x, t = threadIdx.x;
    float Sacc[8];
#pragma unroll
    for (int i = 0; i < 8; i++) {
        int e = t + 512 * i;
        float s = 0.f;
#pragma unroll
        for (int sl = 0; sl < 16; sl++) s += g_Sp[(size_t)(sl * 32 + b) * 4096 + e];
        Sacc[i] = s;
    }
    if (t < 64) {
        float m2 = 0.f;
#pragma unroll
        for (int sl = 0; sl < 16; sl++) m2 += g_csp[(sl * 32 + b) * 64 + t];
        smean[t] = m2 * (1.f / 16384.f);
    }
    if (t == 0) s_tr = 0.f;
    __syncthreads();
#pragma unroll
    for (int i = 0; i < 8; i++) {
        int e = t + 512 * i, g = e >> 6, h = e & 63;
        sigN[g * 68 + h] = Sacc[i] * (1.f / 16384.f) - smean[g] * smean[h];
        bA[g * 68 + h] = (g == h) ? 1.f : 0.f;
    }
    __syncthreads();
    if (t < 64) atomicAdd(&s_tr, sigN[t * 68 + t]);
    __syncthreads();
    float trinv = 1.f / s_tr;
#pragma unroll
    for (int i = 0; i < 8; i++) {
        int e = t + 512 * i;
        sigN[(e >> 6) * 68 + (e & 63)] *= trinv;
    }
    __syncthreads();
    float *p = bA, *t1 = bB, *t2 = bC;
    for (int it = 0; it < 5; it++) {
        mm64h(p, sigN, t1, t, false); __syncthreads();
        mm64h(p, t1, t2, t, false);   __syncthreads();
        mm64h(p, t2, t1, t, true);    __syncthreads();
        float* tmp = p; p = t1; t1 = tmp;
    }
    float sq = sqrtf(trinv);
#pragma unroll
    for (int i = 0; i < 8; i++) {
        int e = t + 512 * i;
        g_wm[b * 4096 + e] = p[(e >> 6) * 68 + (e & 63)] * sq;
    }
    if (t < 64) g_mean[b * 64 + t] = smean[t];
}

// ---------------- K2b: cross-batch sqrt-variance (ddof=1), once --------------
__global__ void k2b_var() {
    int e = blockIdx.x * 256 + threadIdx.x;
    if (e < 4096) {
        float v[32], mu = 0.f;
#pragma unroll
        for (int b = 0; b < 32; b++) { v[b] = g_wm[b * 4096 + e]; mu += v[b]; }
        mu *= (1.f / 32.f);
        float s = 0.f;
#pragma unroll
        for (int b = 0; b < 32; b++) { float d = v[b] - mu; s += d * d; }
        g_svw[e] = sqrtf(s * (1.f / 31.f) + EPSV);
    } else if (e < 4160) {
        int g = e - 4096;
        float v[32], mu = 0.f;
#pragma unroll
        for (int b = 0; b < 32; b++) { v[b] = g_mean[b * 64 + g]; mu += v[b]; }
        mu *= (1.f / 32.f);
        float s = 0.f;
#pragma unroll
        for (int b = 0; b < 32; b++) { float d = v[b] - mu; s += d * d; }
        g_svm[g] = sqrtf(s * (1.f / 31.f) + EPSV);
    }
}

// ------- K2c: gamma + A = gamma@wm + beta', 2 blocks per batch (row halves) --
__global__ __launch_bounds__(256) void k2c_gamma(const float* __restrict__ eps1,
                                                 const float* __restrict__ eps2) {
    extern __shared__ float sm[];
    float* W  = sm;          // 64 x 68 (full wm)
    float* Gm = sm + 4352;   // 32 x 68 (gamma rows of this half)
    float* Am = sm + 6528;   // 32 x 68
    __shared__ float smean[64];
    int hf = blockIdx.x, b = blockIdx.y, t = threadIdx.x;
    int rb = hf * 32;
    if (t < 64) smean[t] = g_mean[b * 64 + t];
#pragma unroll
    for (int i = 0; i < 16; i++) {
        int e = t + 256 * i;
        W[(e >> 6) * 68 + (e & 63)] = g_wm[b * 4096 + e];
    }
    __syncthreads();
#pragma unroll
    for (int i = 0; i < 8; i++) {
        int e = t + 256 * i, gl = e >> 6, h = e & 63, g = rb + gl;
        int gg = (g <= h) ? g : h, hh = (g <= h) ? h : g;
        int ep = gg * 64 + hh;
        Gm[gl * 68 + h] = W[gg * 68 + hh] + eps1[b * 4096 + ep] * g_svw[ep];
    }
    __syncthreads();
    // Am(32x64) = Gm(32x64) @ W(64x64); thread tile 2 rows x 4 cols
    {
        int r0 = (t >> 4) << 1, c0 = t & 15;
        float acc[8];
#pragma unroll
        for (int i = 0; i < 8; i++) acc[i] = 0.f;
#pragma unroll 8
        for (int k = 0; k < 64; k++) {
            float a0 = Gm[(r0 + 0) * 68 + k], a1 = Gm[(r0 + 1) * 68 + k];
            float b0 = W[k * 68 + c0],      b1 = W[k * 68 + c0 + 16];
            float b2 = W[k * 68 + c0 + 32], b3 = W[k * 68 + c0 + 48];
            acc[0] += a0*b0; acc[1] += a0*b1; acc[2] += a0*b2; acc[3] += a0*b3;
            acc[4] += a1*b0; acc[5] += a1*b1; acc[6] += a1*b2; acc[7] += a1*b3;
        }
#pragma unroll
        for (int i = 0; i < 2; i++)
#pragma unroll
            for (int j = 0; j < 4; j++)
                Am[(r0 + i) * 68 + c0 + 16 * j] = acc[i * 4 + j];
    }
    __syncthreads();
#pragma unroll
    for (int i = 0; i < 8; i++) {
        int e = t + 256 * i;
        g_A[b * 4096 + rb * 64 + e] = __uint_as_float(t32(Am[(e >> 6) * 68 + (e & 63)]));
    }
    if (t < 32) {
        int row = rb + t;
        float s = 0.f;
        for (int h = 0; h < 64; h++) s += Am[t * 68 + h] * smean[h];
        g_bp[b * 64 + row] = smean[row] + eps2[b * 64 + row] * g_svm[row] - s;
    }
}

// ---- K3: y = A@xs + beta', A-frags hoisted in regs, 3-stage cp.async --------
// grid (16 slices, 32 batches), 256 thr; block 64 rows x 1024 cols, chunk 64.
__global__ __launch_bounds__(256) void k3_apply(const float* __restrict__ x,
                                                const int* __restrict__ idx,
                                                float* __restrict__ out) {
    extern __shared__ float sm[];   // 3 stages of 64x72
    __shared__ const float* rowp[64];
    __shared__ float* outp[64];
    __shared__ float bps[64];
    int sl = blockIdx.x, b = blockIdx.y, t = threadIdx.x;
    if (t < 64) {
        size_t off = ((size_t)(b * 256 + idx[4 * t + (sl >> 2)])) * 4096 + (sl & 3) * 1024;
        rowp[t] = x + off;
        outp[t] = out + off;
        bps[t] = g_bp[b * 64 + t];
    }
    __syncthreads();
    int r = t >> 2, fq = t & 3;
    const float* rp = rowp[r];
    unsigned sb = (unsigned)__cvta_generic_to_shared(sm);
#pragma unroll
    for (int s = 0; s < 2; s++) {
        unsigned d = sb + (s * 4608 + r * 72 + fq * 4) * 4;
        const float* src = rp + s * 64 + fq * 4;
#pragma unroll
        for (int j = 0; j < 4; j++) cpa16(d + j * 64, src + j * 16);
        asm volatile("cp.async.commit_group;");
    }
    int lane = t & 31, w = t >> 5, g = lane >> 2, tg = lane & 3;
    int mbase = (w & 3) * 16, cb = (w >> 2) * 32;
    int r0 = mbase + g, r1 = r0 + 8;
    // hoist all A fragments (g_A is tf32-rounded, L2-resident)
    const float* Ab = g_A + b * 4096;
    unsigned afr[8][4];
#pragma unroll
    for (int k0 = 0; k0 < 8; k0++) {
        afr[k0][0] = __float_as_uint(__ldg(Ab + r0 * 64 + k0 * 8 + tg));
        afr[k0][1] = __float_as_uint(__ldg(Ab + r1 * 64 + k0 * 8 + tg));
        afr[k0][2] = __float_as_uint(__ldg(Ab + r0 * 64 + k0 * 8 + tg + 4));
        afr[k0][3] = __float_as_uint(__ldg(Ab + r1 * 64 + k0 * 8 + tg + 4));
    }
    float* o0 = outp[r0];
    float* o1 = outp[r1];
    float bp0 = bps[r0], bp1 = bps[r1];
    for (int c = 0; c < 16; c++) {
        if (c < 15) { asm volatile("cp.async.wait_group 1;"); }
        else        { asm volatile("cp.async.wait_group 0;"); }
        __syncthreads();
        const float* Xc = sm + (c % 3) * 4608;
        float acc[4][4];
#pragma unroll
        for (int j = 0; j < 4; j++)
#pragma unroll
            for (int i = 0; i < 4; i++) acc[j][i] = 0.f;
#pragma unroll
        for (int k0 = 0; k0 < 8; k0++) {
#pragma unroll
            for (int j = 0; j < 4; j++) {
                unsigned b0 = __float_as_uint(Xc[(k0 * 8 + tg) * 72 + cb + j * 8 + g]);
                unsigned b1 = __float_as_uint(Xc[(k0 * 8 + tg + 4) * 72 + cb + j * 8 + g]);
                mma8(acc[j], afr[k0], b0, b1);
            }
        }
#pragma unroll
        for (int j = 0; j < 4; j++) {
            int col = c * 64 + cb + j * 8 + 2 * tg;
            *(float2*)(o0 + col) = make_float2(acc[j][0] + bp0, acc[j][1] + bp0);
            *(float2*)(o1 + col) = make_float2(acc[j][2] + bp1, acc[j][3] + bp1);
        }
        if (c < 14) {
            unsigned d = sb + (((c + 2) % 3) * 4608 + r * 72 + fq * 4) * 4;
            const float* src = rp + (c + 2) * 64 + fq * 4;
#pragma unroll
            for (int j = 0; j < 4; j++) cpa16(d + j * 64, src + j * 16);
            asm volatile("cp.async.commit_group;");
        }
    }
}

extern "C" void kernel_launch(void* const* d_in, const int* in_sizes, int n_in,
                              void* d_out, int out_size) {
    const float* x    = (const float*)d_in[0];
    const int*   idx  = (const int*)d_in[1];
    const float* eps1 = (const float*)d_in[2];
    const float* eps2 = (const float*)d_in[3];
    float* out = (float*)d_out;
    cudaFuncSetAttribute(k1_gram,   cudaFuncAttributeMaxDynamicSharedMemorySize, 52224);
    cudaFuncSetAttribute(k2a_ns,    cudaFuncAttributeMaxDynamicSharedMemorySize, 69632);
    cudaFuncSetAttribute(k2c_gamma, cudaFuncAttributeMaxDynamicSharedMemorySize, 34816);
    cudaFuncSetAttribute(k3_apply,  cudaFuncAttributeMaxDynamicSharedMemorySize, 55296);
    k1_gram<<<dim3(16, 32), 256, 52224>>>(x, idx);
    k2a_ns<<<32, 512, 69632>>>();
    k2b_var<<<17, 256>>>();
    k2c_gamma<<<dim3(2, 32), 256, 34816>>>(eps1, eps2);
    k3_apply<<<dim3(16, 32), 256, 55296>>>(x, idx, out);
}

// round 16
// speedup vs baseline: 1.1413x; 1.1413x over previous
#include <cuda_runtime.h>
#include <cstdint>

#define EPSV 1e-5f

__device__ __align__(16) float g_Sp[16*32*4096];   // per-slice partial Grams
__device__ __align__(16) float g_csp[16*32*64];    // per-slice partial col sums
__device__ __align__(16) float g_wm[32*4096];
__device__ __align__(16) float g_mean[2048];
__device__ __align__(16) float g_svw[4096];
__device__ __align__(16) float g_svm[64];
__device__ __align__(16) float g_A[32*4096];       // stored tf32-rounded
__device__ __align__(16) float g_bp[2048];

__device__ __forceinline__ unsigned t32(float x) {
    unsigned r; asm("cvt.rna.tf32.f32 %0,%1;" : "=r"(r) : "f"(x)); return r;
}
__device__ __forceinline__ void mma8(float* c, const unsigned* a, unsigned b0, unsigned b1) {
    asm("mma.sync.aligned.m16n8k8.row.col.f32.tf32.tf32.f32 "
        "{%0,%1,%2,%3},{%4,%5,%6,%7},{%8,%9},{%0,%1,%2,%3};"
        : "+f"(c[0]), "+f"(c[1]), "+f"(c[2]), "+f"(c[3])
        : "r"(a[0]), "r"(a[1]), "r"(a[2]), "r"(a[3]), "r"(b0), "r"(b1));
}
__device__ __forceinline__ void cpa16(unsigned d, const float* s) {
    asm volatile("cp.async.ca.shared.global [%0],[%1],16;" :: "r"(d), "l"(s));
}

// ---- K1: Gram partials, mma.tf32, 32x32 warp tiles with k-split (2 LDS/MMA) -
// grid (16 slices, 32 batches), 256 thr; block = 64 rows x 1024 cols, chunk 64.
// Warps 0-3: quadrants, k0=0..3.  Warps 4-7: same quadrants, k0=4..7.
// Accumulators persist across chunks; one smem reduction merges k-halves.
__global__ __launch_bounds__(256) void k1_gram(const float* __restrict__ x,
                                               const int* __restrict__ idx) {
    extern __shared__ float sm[];            // 2 x (64*68)
    __shared__ const float* rowp[64];
    int sl = blockIdx.x, b = blockIdx.y, t = threadIdx.x;
    if (t < 64)
        rowp[t] = x + ((size_t)(b * 256 + idx[4 * t + (sl >> 2)])) * 4096 + (sl & 3) * 1024;
    __syncthreads();
    int r = t >> 2, fq = t & 3;
    const float* rp = rowp[r];
    unsigned sb = (unsigned)__cvta_generic_to_shared(sm);
    unsigned d0 = sb + (r * 68 + fq * 4) * 4;
#pragma unroll
    for (int j = 0; j < 4; j++) cpa16(d0 + j * 64, rp + fq * 4 + j * 16);
    asm volatile("cp.async.commit_group;");
    int lane = t & 31, w = t >> 5, g = lane >> 2, tg = lane & 3;
    int ksel = w >> 2, mrow = (w & 1) * 32, ncol = ((w >> 1) & 1) * 32;
    float acc[2][4][4];
#pragma unroll
    for (int mf = 0; mf < 2; mf++)
#pragma unroll
        for (int nf = 0; nf < 4; nf++)
#pragma unroll
            for (int i = 0; i < 4; i++) acc[mf][nf][i] = 0.f;
    float cs = 0.f;
    for (int c = 0; c < 16; c++) {
        if (c < 15) {
            unsigned d = sb + (((c + 1) & 1) * 4352 + r * 68 + fq * 4) * 4;
            const float* s = rp + (c + 1) * 64 + fq * 4;
#pragma unroll
            for (int j = 0; j < 4; j++) cpa16(d + j * 64, s + j * 16);
            asm volatile("cp.async.commit_group;");
            asm volatile("cp.async.wait_group 1;");
        } else {
            asm volatile("cp.async.wait_group 0;");
        }
        __syncthreads();
        const float* Xc = sm + (c & 1) * 4352;
#pragma unroll
        for (int j = 0; j < 4; j++) {
            float4 v = *(const float4*)(Xc + r * 68 + fq * 16 + j * 4);
            cs += v.x + v.y + v.z + v.w;
        }
#pragma unroll
        for (int kk = 0; kk < 4; kk++) {
            int kb = (ksel * 4 + kk) * 8 + tg;
            unsigned a0[4], a1[4];
            a0[0] = __float_as_uint(Xc[(mrow + g) * 68 + kb]);
            a0[1] = __float_as_uint(Xc[(mrow + g + 8) * 68 + kb]);
            a0[2] = __float_as_uint(Xc[(mrow + g) * 68 + kb + 4]);
            a0[3] = __float_as_uint(Xc[(mrow + g + 8) * 68 + kb + 4]);
            a1[0] = __float_as_uint(Xc[(mrow + 16 + g) * 68 + kb]);
            a1[1] = __float_as_uint(Xc[(mrow + 24 + g) * 68 + kb]);
            a1[2] = __float_as_uint(Xc[(mrow + 16 + g) * 68 + kb + 4]);
            a1[3] = __float_as_uint(Xc[(mrow + 24 + g) * 68 + kb + 4]);
#pragma unroll
            for (int nf = 0; nf < 4; nf++) {
                int n = ncol + nf * 8 + g;
                unsigned b0 = __float_as_uint(Xc[n * 68 + kb]);
                unsigned b1 = __float_as_uint(Xc[n * 68 + kb + 4]);
                mma8(acc[0][nf], a0, b0, b1);
                mma8(acc[1][nf], a1, b0, b1);
            }
        }
        __syncthreads();
    }
    // merge k-halves: ksel=1 stages to smem (stage 0, loop done), ksel=0 adds
    float* red = sm;
    if (ksel == 1) {
#pragma unroll
        for (int mf = 0; mf < 2; mf++)
#pragma unroll
            for (int nf = 0; nf < 4; nf++) {
                int row = mrow + mf * 16 + g, col = ncol + nf * 8 + 2 * tg;
                *(float2*)&red[row * 68 + col]       = make_float2(acc[mf][nf][0], acc[mf][nf][1]);
                *(float2*)&red[(row + 8) * 68 + col] = make_float2(acc[mf][nf][2], acc[mf][nf][3]);
            }
    }
    __syncthreads();
    if (ksel == 0) {
        float* dst = g_Sp + (size_t)(sl * 32 + b) * 4096;
#pragma unroll
        for (int mf = 0; mf < 2; mf++)
#pragma unroll
            for (int nf = 0; nf < 4; nf++) {
                int row = mrow + mf * 16 + g, col = ncol + nf * 8 + 2 * tg;
                float2 p0 = *(float2*)&red[row * 68 + col];
                float2 p1 = *(float2*)&red[(row + 8) * 68 + col];
                *(float2*)(dst + row * 64 + col) =
                    make_float2(acc[mf][nf][0] + p0.x, acc[mf][nf][1] + p0.y);
                *(float2*)(dst + (row + 8) * 64 + col) =
                    make_float2(acc[mf][nf][2] + p1.x, acc[mf][nf][3] + p1.y);
            }
    }
    cs += __shfl_down_sync(0xffffffffu, cs, 2, 4);
    cs += __shfl_down_sync(0xffffffffu, cs, 1, 4);
    if (fq == 0) g_csp[(sl * 32 + b) * 64 + r] = cs;
}

// ---- 64x64 smem matmul, LD=68, A k-vectorized (float4), 256 threads ---------
#define MMK(COMP, BK) { \
    float b0 = (BK)[0], b1 = (BK)[16], b2 = (BK)[32], b3 = (BK)[48]; \
    acc[0] += va0.COMP*b0; acc[1] += va0.COMP*b1; acc[2]  += va0.COMP*b2; acc[3]  += va0.COMP*b3; \
    acc[4] += va1.COMP*b0; acc[5] += va1.COMP*b1; acc[6]  += va1.COMP*b2; acc[7]  += va1.COMP*b3; \
    acc[8] += va2.COMP*b0; acc[9] += va2.COMP*b1; acc[10] += va2.COMP*b2; acc[11] += va2.COMP*b3; \
    acc[12]+= va3.COMP*b0; acc[13]+= va3.COMP*b1; acc[14] += va3.COMP*b2; acc[15] += va3.COMP*b3; }

__device__ __forceinline__ void mm64v(const float* __restrict__ A,
                                      const float* __restrict__ B,
                                      float* __restrict__ C, int t, bool fin) {
    int r0 = (t >> 4) << 2, c0 = t & 15;
    float acc[16];
#pragma unroll
    for (int i = 0; i < 16; i++) acc[i] = 0.f;
#pragma unroll
    for (int k4 = 0; k4 < 16; k4++) {
        float4 va0 = *(const float4*)(A + (r0 + 0) * 68 + k4 * 4);
        float4 va1 = *(const float4*)(A + (r0 + 1) * 68 + k4 * 4);
        float4 va2 = *(const float4*)(A + (r0 + 2) * 68 + k4 * 4);
        float4 va3 = *(const float4*)(A + (r0 + 3) * 68 + k4 * 4);
        const float* Bk = B + k4 * 4 * 68 + c0;
        MMK(x, Bk); Bk += 68;
        MMK(y, Bk); Bk += 68;
        MMK(z, Bk); Bk += 68;
        MMK(w, Bk);
    }
#pragma unroll
    for (int i = 0; i < 4; i++)
#pragma unroll
        for (int j = 0; j < 4; j++) {
            int ci = (r0 + i) * 68 + c0 + 16 * j;
            C[ci] = fin ? (1.5f * A[ci] - 0.5f * acc[i * 4 + j]) : acc[i * 4 + j];
        }
}

// ---------------- K2a: reduce partials -> sigma -> Newton-Schulz -> wm -------
__global__ __launch_bounds__(256) void k2a_ns() {
    extern __shared__ float sm[];
    float* sigN = sm;
    float* bA = sm + 4352;
    float* bB = sm + 8704;
    float* bC = sm + 13056;
    __shared__ float smean[64];
    __shared__ float s_tr;
    int b = blockIdx.x, t = threadIdx.x;
    float Sacc[16];
#pragma unroll
    for (int i = 0; i < 16; i++) {
        int e = t + 256 * i;
        float s = 0.f;
#pragma unroll
        for (int sl = 0; sl < 16; sl++) s += g_Sp[(size_t)(sl * 32 + b) * 4096 + e];
        Sacc[i] = s;
    }
    if (t < 64) {
        float m2 = 0.f;
#pragma unroll
        for (int sl = 0; sl < 16; sl++) m2 += g_csp[(sl * 32 + b) * 64 + t];
        smean[t] = m2 * (1.f / 16384.f);
    }
    if (t == 0) s_tr = 0.f;
    __syncthreads();
#pragma unroll
    for (int i = 0; i < 16; i++) {
        int e = t + 256 * i, g = e >> 6, h = e & 63;
        sigN[g * 68 + h] = Sacc[i] * (1.f / 16384.f) - smean[g] * smean[h];
        bA[g * 68 + h] = (g == h) ? 1.f : 0.f;
    }
    __syncthreads();
    if (t < 64) atomicAdd(&s_tr, sigN[t * 68 + t]);
    __syncthreads();
    float trinv = 1.f / s_tr;
#pragma unroll
    for (int i = 0; i < 16; i++) {
        int e = t + 256 * i;
        sigN[(e >> 6) * 68 + (e & 63)] *= trinv;
    }
    __syncthreads();
    float *p = bA, *t1 = bB, *t2 = bC;
    for (int it = 0; it < 5; it++) {
        mm64v(p, sigN, t1, t, false); __syncthreads();
        mm64v(p, t1, t2, t, false);   __syncthreads();
        mm64v(p, t2, t1, t, true);    __syncthreads();
        float* tmp = p; p = t1; t1 = tmp;
    }
    float sq = sqrtf(trinv);
#pragma unroll
    for (int i = 0; i < 16; i++) {
        int e = t + 256 * i;
        g_wm[b * 4096 + e] = p[(e >> 6) * 68 + (e & 63)] * sq;
    }
    if (t < 64) g_mean[b * 64 + t] = smean[t];
}

// ---------------- K2b: cross-batch sqrt-variance (ddof=1), once --------------
__global__ void k2b_var() {
    int e = blockIdx.x * 256 + threadIdx.x;
    if (e < 4096) {
        float v[32], mu = 0.f;
#pragma unroll
        for (int b = 0; b < 32; b++) { v[b] = g_wm[b * 4096 + e]; mu += v[b]; }
        mu *= (1.f / 32.f);
        float s = 0.f;
#pragma unroll
        for (int b = 0; b < 32; b++) { float d = v[b] - mu; s += d * d; }
        g_svw[e] = sqrtf(s * (1.f / 31.f) + EPSV);
    } else if (e < 4160) {
        int g = e - 4096;
        float v[32], mu = 0.f;
#pragma unroll
        for (int b = 0; b < 32; b++) { v[b] = g_mean[b * 64 + g]; mu += v[b]; }
        mu *= (1.f / 32.f);
        float s = 0.f;
#pragma unroll
        for (int b = 0; b < 32; b++) { float d = v[b] - mu; s += d * d; }
        g_svm[g] = sqrtf(s * (1.f / 31.f) + EPSV);
    }
}

// ------- K2c: gamma + A = gamma@wm + beta', 2 blocks per batch (row halves) --
__global__ __launch_bounds__(256) void k2c_gamma(const float* __restrict__ eps1,
                                                 const float* __restrict__ eps2) {
    extern __shared__ float sm[];
    float* W  = sm;          // 64 x 68 (full wm)
    float* Gm = sm + 4352;   // 32 x 68 (gamma rows of this half)
    float* Am = sm + 6528;   // 32 x 68
    __shared__ float smean[64];
    int hf = blockIdx.x, b = blockIdx.y, t = threadIdx.x;
    int rb = hf * 32;
    if (t < 64) smean[t] = g_mean[b * 64 + t];
#pragma unroll
    for (int i = 0; i < 16; i++) {
        int e = t + 256 * i;
        W[(e >> 6) * 68 + (e & 63)] = g_wm[b * 4096 + e];
    }
    __syncthreads();
#pragma unroll
    for (int i = 0; i < 8; i++) {
        int e = t + 256 * i, gl = e >> 6, h = e & 63, g = rb + gl;
        int gg = (g <= h) ? g : h, hh = (g <= h) ? h : g;
        int ep = gg * 64 + hh;
        Gm[gl * 68 + h] = W[gg * 68 + hh] + eps1[b * 4096 + ep] * g_svw[ep];
    }
    __syncthreads();
    // Am(32x64) = Gm(32x64) @ W(64x64); thread tile 2 rows x 4 cols
    {
        int r0 = (t >> 4) << 1, c0 = t & 15;
        float acc[8];
#pragma unroll
        for (int i = 0; i < 8; i++) acc[i] = 0.f;
#pragma unroll 8
        for (int k = 0; k < 64; k++) {
            float a0 = Gm[(r0 + 0) * 68 + k], a1 = Gm[(r0 + 1) * 68 + k];
            float b0 = W[k * 68 + c0],      b1 = W[k * 68 + c0 + 16];
            float b2 = W[k * 68 + c0 + 32], b3 = W[k * 68 + c0 + 48];
            acc[0] += a0*b0; acc[1] += a0*b1; acc[2] += a0*b2; acc[3] += a0*b3;
            acc[4] += a1*b0; acc[5] += a1*b1; acc[6] += a1*b2; acc[7] += a1*b3;
        }
#pragma unroll
        for (int i = 0; i < 2; i++)
#pragma unroll
            for (int j = 0; j < 4; j++)
                Am[(r0 + i) * 68 + c0 + 16 * j] = acc[i * 4 + j];
    }
    __syncthreads();
#pragma unroll
    for (int i = 0; i < 8; i++) {
        int e = t + 256 * i;
        g_A[b * 4096 + rb * 64 + e] = __uint_as_float(t32(Am[(e >> 6) * 68 + (e & 63)]));
    }
    if (t < 32) {
        int row = rb + t;
        float s = 0.f;
        for (int h = 0; h < 64; h++) s += Am[t * 68 + h] * smean[h];
        g_bp[b * 64 + row] = smean[row] + eps2[b * 64 + row] * g_svm[row] - s;
    }
}

// ---- K3: y = A@xs + beta', A-frags hoisted in regs, 3-stage cp.async --------
// grid (16 slices, 32 batches), 256 thr; block 64 rows x 1024 cols, chunk 64.
__global__ __launch_bounds__(256) void k3_apply(const float* __restrict__ x,
                                                const int* __restrict__ idx,
                                                float* __restrict__ out) {
    extern __shared__ float sm[];   // 3 stages of 64x72
    __shared__ const float* rowp[64];
    __shared__ float* outp[64];
    __shared__ float bps[64];
    int sl = blockIdx.x, b = blockIdx.y, t = threadIdx.x;
    if (t < 64) {
        size_t off = ((size_t)(b * 256 + idx[4 * t + (sl >> 2)])) * 4096 + (sl & 3) * 1024;
        rowp[t] = x + off;
        outp[t] = out + off;
        bps[t] = g_bp[b * 64 + t];
    }
    __syncthreads();
    int r = t >> 2, fq = t & 3;
    const float* rp = rowp[r];
    unsigned sb = (unsigned)__cvta_generic_to_shared(sm);
#pragma unroll
    for (int s = 0; s < 2; s++) {
        unsigned d = sb + (s * 4608 + r * 72 + fq * 4) * 4;
        const float* src = rp + s * 64 + fq * 4;
#pragma unroll
        for (int j = 0; j < 4; j++) cpa16(d + j * 64, src + j * 16);
        asm volatile("cp.async.commit_group;");
    }
    int lane = t & 31, w = t >> 5, g = lane >> 2, tg = lane & 3;
    int mbase = (w & 3) * 16, cb = (w >> 2) * 32;
    int r0 = mbase + g, r1 = r0 + 8;
    // hoist all A fragments (g_A is tf32-rounded, L2-resident)
    const float* Ab = g_A + b * 4096;
    unsigned afr[8][4];
#pragma unroll
    for (int k0 = 0; k0 < 8; k0++) {
        afr[k0][0] = __float_as_uint(__ldg(Ab + r0 * 64 + k0 * 8 + tg));
        afr[k0][1] = __float_as_uint(__ldg(Ab + r1 * 64 + k0 * 8 + tg));
        afr[k0][2] = __float_as_uint(__ldg(Ab + r0 * 64 + k0 * 8 + tg + 4));
        afr[k0][3] = __float_as_uint(__ldg(Ab + r1 * 64 + k0 * 8 + tg + 4));
    }
    float* o0 = outp[r0];
    float* o1 = outp[r1];
    float bp0 = bps[r0], bp1 = bps[r1];
    for (int c = 0; c < 16; c++) {
        if (c < 15) { asm volatile("cp.async.wait_group 1;"); }
        else        { asm volatile("cp.async.wait_group 0;"); }
        __syncthreads();
        const float* Xc = sm + (c % 3) * 4608;
        float acc[4][4];
#pragma unroll
        for (int j = 0; j < 4; j++)
#pragma unroll
            for (int i = 0; i < 4; i++) acc[j][i] = 0.f;
#pragma unroll
        for (int k0 = 0; k0 < 8; k0++) {
#pragma unroll
            for (int j = 0; j < 4; j++) {
                unsigned b0 = __float_as_uint(Xc[(k0 * 8 + tg) * 72 + cb + j * 8 + g]);
                unsigned b1 = __float_as_uint(Xc[(k0 * 8 + tg + 4) * 72 + cb + j * 8 + g]);
                mma8(acc[j], afr[k0], b0, b1);
            }
        }
#pragma unroll
        for (int j = 0; j < 4; j++) {
            int col = c * 64 + cb + j * 8 + 2 * tg;
            *(float2*)(o0 + col) = make_float2(acc[j][0] + bp0, acc[j][1] + bp0);
            *(float2*)(o1 + col) = make_float2(acc[j][2] + bp1, acc[j][3] + bp1);
        }
        if (c < 14) {
            unsigned d = sb + (((c + 2) % 3) * 4608 + r * 72 + fq * 4) * 4;
            const float* src = rp + (c + 2) * 64 + fq * 4;
#pragma unroll
            for (int j = 0; j < 4; j++) cpa16(d + j * 64, src + j * 16);
            asm volatile("cp.async.commit_group;");
        }
    }
}

extern "C" void kernel_launch(void* const* d_in, const int* in_sizes, int n_in,
                              void* d_out, int out_size) {
    const float* x    = (const float*)d_in[0];
    const int*   idx  = (const int*)d_in[1];
    const float* eps1 = (const float*)d_in[2];
    const float* eps2 = (const float*)d_in[3];
    float* out = (float*)d_out;
    cudaFuncSetAttribute(k2a_ns,    cudaFuncAttributeMaxDynamicSharedMemorySize, 69632);
    cudaFuncSetAttribute(k2c_gamma, cudaFuncAttributeMaxDynamicSharedMemorySize, 34816);
    cudaFuncSetAttribute(k3_apply,  cudaFuncAttributeMaxDynamicSharedMemorySize, 55296);
    k1_gram<<<dim3(16, 32), 256, 34816>>>(x, idx);
    k2a_ns<<<32, 256, 69632>>>();
    k2b_var<<<17, 256>>>();
    k2c_gamma<<<dim3(2, 32), 256, 34816>>>(eps1, eps2);
    k3_apply<<<dim3(16, 32), 256, 55296>>>(x, idx, out);
}